// round 13
// baseline (speedup 1.0000x reference)
#include <cuda_runtime.h>
#include <cuda_fp16.h>
#include <cstdint>

#define TM       64
#define THREADS  256
#define IN_DIM   472
#define HID      128

// ---- smem byte offsets ----
#define A_OFF    0
#define ACS      144                    // A chunk row stride: 64k fp16 = 128B + 16B pad
#define ABUF_STRIDE (64 * ACS)          // 9216 per chunk slot
#define W_OFF    (2 * ABUF_STRIDE)      // 18432
#define WNS      144                    // W n-row stride
#define WBUF_STRIDE (128 * WNS)         // 18432
#define TW_OFF   55296
#define TB_OFF   55696
#define B1_OFF   56096
#define W2_OFF   56608
#define SRC_OFF  57120
#define DST_OFF  57376
#define DT_OFF   57632
#define PART_OFF 57888
#define SMEM_BYTES 58912                // x3 CTA = 176736 <= 228KB

__device__ __align__(16) __half g_w[128 * 512];   // [n][k] fp16

typedef unsigned long long ull;

// ---------------- helpers ----------------
__device__ __forceinline__ uint32_t smem_u32(const void* p) {
    uint32_t a;
    asm("{ .reg .u64 t; cvta.to.shared.u64 t, %1; cvt.u32.u64 %0, t; }" : "=r"(a) : "l"(p));
    return a;
}
__device__ __forceinline__ void ldsm4(uint32_t* r, uint32_t a) {
    asm volatile("ldmatrix.sync.aligned.m8n8.x4.shared.b16 {%0,%1,%2,%3}, [%4];"
        : "=r"(r[0]), "=r"(r[1]), "=r"(r[2]), "=r"(r[3]) : "r"(a));
}
__device__ __forceinline__ void mma16816(float* d, const uint32_t* a, uint32_t b0, uint32_t b1) {
    asm volatile("mma.sync.aligned.m16n8k16.row.col.f32.f16.f16.f32 "
        "{%0,%1,%2,%3}, {%4,%5,%6,%7}, {%8,%9}, {%0,%1,%2,%3};"
        : "+f"(d[0]), "+f"(d[1]), "+f"(d[2]), "+f"(d[3])
        : "r"(a[0]), "r"(a[1]), "r"(a[2]), "r"(a[3]), "r"(b0), "r"(b1));
}
__device__ __forceinline__ void cpasync16(uint32_t s, const void* g) {
    asm volatile("cp.async.cg.shared.global [%0], [%1], 16;" :: "r"(s), "l"(g) : "memory");
}
#define CP_COMMIT() asm volatile("cp.async.commit_group;" ::: "memory")
#define CP_WAIT0()  asm volatile("cp.async.wait_group 0;" ::: "memory")

// ---- packed f32x2 ops ----
__device__ __forceinline__ ull pk2(float x, float y) {
    ull r; asm("mov.b64 %0, {%1, %2};" : "=l"(r) : "f"(x), "f"(y)); return r;
}
__device__ __forceinline__ void upk2(ull v, float& x, float& y) {
    asm("mov.b64 {%0, %1}, %2;" : "=f"(x), "=f"(y) : "l"(v));
}
__device__ __forceinline__ ull fma2(ull a, ull b, ull c) {
    ull d; asm("fma.rn.f32x2 %0, %1, %2, %3;" : "=l"(d) : "l"(a), "l"(b), "l"(c)); return d;
}
__device__ __forceinline__ ull mul2(ull a, ull b) {
    ull d; asm("mul.rn.f32x2 %0, %1, %2;" : "=l"(d) : "l"(a), "l"(b)); return d;
}
__device__ __forceinline__ ull add2(ull a, ull b) {
    ull d; asm("add.rn.f32x2 %0, %1, %2;" : "=l"(d) : "l"(a), "l"(b)); return d;
}
__device__ __forceinline__ ull sub2(ull a, ull b) {
    ull d; asm("sub.rn.f32x2 %0, %1, %2;" : "=l"(d) : "l"(a), "l"(b)); return d;
}

// one packed poly-cos chain: returns cos(x) for packed pair x
__device__ __forceinline__ ull polyChain(ull x) {
    const float inv = 0.15915494309189535f;
    const float mg  = 12582912.0f;
    const ull INV2 = pk2(inv, inv), MAG2 = pk2(mg, mg);
    const ull C1 = pk2(-19.739208802178716f, -19.739208802178716f);
    const ull C2 = pk2( 64.93939402266829f,   64.93939402266829f);
    const ull C3 = pk2(-85.45681720669371f,  -85.45681720669371f);
    const ull C4 = pk2( 60.24464137187666f,   60.24464137187666f);
    const ull C5 = pk2(-26.42625678337438f,  -26.42625678337438f);
    const ull C6 = pk2(  7.903536371318467f,   7.903536371318467f);
    const ull C7 = pk2( -1.714390711088671f,  -1.714390711088671f);
    const ull C0 = pk2(1.0f, 1.0f);
    ull tq = mul2(x, INV2);
    ull kq = add2(tq, MAG2);
    ull nq = sub2(kq, MAG2);
    ull nn = sub2(0ull, nq);
    ull s  = fma2(x, INV2, nn);
    ull u  = mul2(s, s);
    ull P  = fma2(C7, u, C6);
    P = fma2(P, u, C5);
    P = fma2(P, u, C4);
    P = fma2(P, u, C3);
    P = fma2(P, u, C2);
    P = fma2(P, u, C1);
    P = fma2(P, u, C0);
    return P;
}

// ---------------- W prep kernel: fp32 -> fp16, [n][k] ----------------
__global__ void wprep_kernel(const float* __restrict__ w1) {
    int i = blockIdx.x * blockDim.x + threadIdx.x;   // 65536
    int n = i >> 9, k = i & 511;
    float v = (k < IN_DIM) ? w1[(size_t)k * HID + n] : 0.f;
    g_w[(size_t)n * 512 + k] = __float2half(v);
}

// ---------------- main fused kernel ----------------
__global__ void __launch_bounds__(THREADS, 3)
tgn_kernel(const int* __restrict__ src, const int* __restrict__ dst,
           const float* __restrict__ t, const float* __restrict__ edge_attr,
           const float* __restrict__ memory, const float* __restrict__ last_update,
           const float* __restrict__ time_w, const float* __restrict__ time_b,
           const float* __restrict__ b1, const float* __restrict__ w2,
           const float* __restrict__ b2, float* __restrict__ out, int E)
{
    extern __shared__ char sm[];
    const uint32_t smb = smem_u32(sm);
    const int tid  = threadIdx.x;
    const int wid  = tid >> 5;
    const int lane = tid & 31;
    const int eBase = blockIdx.x * TM;

    float* TW   = (float*)(sm + TW_OFF);
    float* TB   = (float*)(sm + TB_OFF);
    float* B1S  = (float*)(sm + B1_OFF);
    float* W2S  = (float*)(sm + W2_OFF);
    int*   SRCI = (int*)(sm + SRC_OFF);
    int*   DSTI = (int*)(sm + DST_OFF);
    float* DTS  = (float*)(sm + DT_OFF);
    float* PART = (float*)(sm + PART_OFF);

    // ---- W chunk copy: 64 k x 128 n fp16 = 16 KB ----
    auto issueW = [&](int g, int b) {
#pragma unroll
        for (int jj = 0; jj < 4; jj++) {
            int idx = tid + THREADS * jj;       // 0..1023
            int n = idx >> 3, k8 = idx & 7;
            const char* gs = (const char*)g_w + ((size_t)n * 512 + g * 64 + k8 * 8) * 2;
            uint32_t sd = smb + W_OFF + b * WBUF_STRIDE + n * WNS + k8 * 16;
            cpasync16(sd, gs);
        }
        CP_COMMIT();
    };
    issueW(0, 0);

    if (tid < 100) { TW[tid] = time_w[tid]; TB[tid] = time_b[tid]; }
    if (tid < HID) { B1S[tid] = b1[tid]; W2S[tid] = w2[tid]; }
    if (tid < TM) {
        int e = eBase + tid;
        int s = 0, d = 0; float dtv = 0.f;
        if (e < E) { s = src[e]; d = dst[e]; dtv = t[e] - last_update[s]; }
        SRCI[tid] = s; DSTI[tid] = d; DTS[tid] = dtv;
    }
    __syncthreads();

    const float4* m4 = reinterpret_cast<const float4*>(memory);     // 25 f4/row
    const float4* e4 = reinterpret_cast<const float4*>(edge_attr);  // 43 f4/row

    // ---- chunk gather: thread -> fixed float4-col (c*16 + tid>>4), rows (tid&15)+16m ----
    auto loadChunk = [&](int c, float4* v) {
        const int j4 = c * 16 + (tid >> 4);     // global float4 col 0..127
        const int rr = tid & 15;
        if (j4 < 25) {
#pragma unroll
            for (int m = 0; m < 4; m++)
                v[m] = m4[(size_t)SRCI[rr + 16 * m] * 25 + j4];
        } else if (j4 < 50) {
            const int cj = j4 - 25;
#pragma unroll
            for (int m = 0; m < 4; m++)
                v[m] = m4[(size_t)DSTI[rr + 16 * m] * 25 + cj];
        } else if (j4 < 75) {
            const int tk = (j4 - 50) * 4;
            if (j4 < 65) {
                const float tw0 = TW[tk],     tb0 = TB[tk];
                const float tw1 = TW[tk + 1], tb1 = TB[tk + 1];
                const float tw2 = TW[tk + 2], tb2 = TB[tk + 2];
                const float tw3 = TW[tk + 3], tb3 = TB[tk + 3];
#pragma unroll
                for (int m = 0; m < 4; m++) {
                    float dtv = DTS[rr + 16 * m];
                    v[m].x = __cosf(fmaf(dtv, tw0, tb0));
                    v[m].y = __cosf(fmaf(dtv, tw1, tb1));
                    v[m].z = __cosf(fmaf(dtv, tw2, tb2));
                    v[m].w = __cosf(fmaf(dtv, tw3, tb3));
                }
            } else {
                const ull TWP0 = pk2(TW[tk],     TW[tk + 1]);
                const ull TBP0 = pk2(TB[tk],     TB[tk + 1]);
                const ull TWP1 = pk2(TW[tk + 2], TW[tk + 3]);
                const ull TBP1 = pk2(TB[tk + 2], TB[tk + 3]);
#pragma unroll
                for (int m = 0; m < 4; m++) {
                    float dtv = DTS[rr + 16 * m];
                    ull dt2 = pk2(dtv, dtv);
                    ull P0 = polyChain(fma2(dt2, TWP0, TBP0));
                    ull P1 = polyChain(fma2(dt2, TWP1, TBP1));
                    upk2(P0, v[m].x, v[m].y);
                    upk2(P1, v[m].z, v[m].w);
                }
            }
        } else if (j4 < 118) {
            const int cj = j4 - 75;
#pragma unroll
            for (int m = 0; m < 4; m++) {
                int er = eBase + rr + 16 * m;
                er = (er < E) ? er : (E - 1);
                v[m] = e4[(size_t)er * 43 + cj];
            }
        } else {
#pragma unroll
            for (int m = 0; m < 4; m++) { v[m].x = 0.f; v[m].y = 0.f; v[m].z = 0.f; v[m].w = 0.f; }
        }
    };
    auto storeChunk = [&](int c, const float4* v) {
        char* base = sm + A_OFF + (c & 1) * ABUF_STRIDE + ((tid >> 4) << 3);
        const int rr = tid & 15;
#pragma unroll
        for (int m = 0; m < 4; m++) {
            __half2 h0 = __floats2half2_rn(v[m].x, v[m].y);
            __half2 h1 = __floats2half2_rn(v[m].z, v[m].w);
            uint2 u;
            u.x = *reinterpret_cast<const uint32_t*>(&h0);
            u.y = *reinterpret_cast<const uint32_t*>(&h1);
            *reinterpret_cast<uint2*>(base + (rr + 16 * m) * ACS) = u;
        }
    };

    // ---- warp tile coordinates: 8 warps = 2 row-groups x 4 col-groups ----
    const int rm = (wid & 1) * 32;
    const int cn = (wid >> 1) * 32;
    const uint32_t aLane = (uint32_t)(rm + (lane & 15)) * ACS
                         + (uint32_t)((lane >> 4) << 4);
    const uint32_t bRow  = (uint32_t)(cn + ((lane >> 4) << 3) + (lane & 7)) * WNS
                         + (uint32_t)(((lane >> 3) & 1) << 4);

    float acc[2][4][4];
#pragma unroll
    for (int ma = 0; ma < 2; ma++)
#pragma unroll
        for (int na = 0; na < 4; na++)
#pragma unroll
            for (int q = 0; q < 4; q++) acc[ma][na][q] = 0.f;

    float4 v[4];
    loadChunk(0, v);

    // ---- 8 chunks of 64 k; A ring + W double buffer; gathers hidden under mma ----
    for (int g = 0; g < 8; g++) {
        CP_WAIT0();
        __syncthreads();                 // W[g&1] landed; all ldsm of chunk g-2 done
        storeChunk(g, v);
        __syncthreads();                 // A[g&1] visible
        if (g < 7) { issueW(g + 1, (g & 1) ^ 1); loadChunk(g + 1, v); }

        const uint32_t bBase = smb + W_OFF + (uint32_t)(g & 1) * WBUF_STRIDE + bRow;
        const uint32_t aB    = smb + A_OFF + (uint32_t)(g & 1) * ABUF_STRIDE + aLane;
#pragma unroll
        for (int ks = 0; ks < 4; ks++) {
            uint32_t ah[8], bh[8];
            ldsm4(ah,     aB + ks * 32);
            ldsm4(ah + 4, aB + 16 * ACS + ks * 32);
            ldsm4(bh,     bBase + ks * 32);
            ldsm4(bh + 4, bBase + 16 * WNS + ks * 32);
#pragma unroll
            for (int ma = 0; ma < 2; ma++)
#pragma unroll
                for (int na = 0; na < 4; na++)
                    mma16816(acc[ma][na], ah + ma * 4, bh[na * 2], bh[na * 2 + 1]);
        }
    }

    // ---- epilogue: bias + ReLU + w2 dot, reduce over n ----
    float p[2][2] = {{0.f, 0.f}, {0.f, 0.f}};
#pragma unroll
    for (int ma = 0; ma < 2; ma++)
#pragma unroll
        for (int na = 0; na < 4; na++) {
            int n0 = cn + na * 8 + ((lane & 3) << 1);
            float b1a = B1S[n0], b1b = B1S[n0 + 1];
            float w2a = W2S[n0], w2b = W2S[n0 + 1];
            float* d = acc[ma][na];
            p[ma][0] += fmaxf(d[0] + b1a, 0.f) * w2a + fmaxf(d[1] + b1b, 0.f) * w2b;
            p[ma][1] += fmaxf(d[2] + b1a, 0.f) * w2a + fmaxf(d[3] + b1b, 0.f) * w2b;
        }
#pragma unroll
    for (int ma = 0; ma < 2; ma++)
#pragma unroll
        for (int rh = 0; rh < 2; rh++) {
            p[ma][rh] += __shfl_xor_sync(0xffffffffu, p[ma][rh], 1);
            p[ma][rh] += __shfl_xor_sync(0xffffffffu, p[ma][rh], 2);
        }
    if ((lane & 3) == 0) {
        int cw = wid >> 1;
        int r0 = rm + (lane >> 2);
        PART[cw * TM + r0]      = p[0][0];
        PART[cw * TM + r0 + 8]  = p[0][1];
        PART[cw * TM + r0 + 16] = p[1][0];
        PART[cw * TM + r0 + 24] = p[1][1];
    }
    __syncthreads();

    if (tid < TM) {
        int e = eBase + tid;
        if (e < E)
            out[e] = PART[tid] + PART[TM + tid] + PART[2 * TM + tid] + PART[3 * TM + tid] + b2[0];
    }
}

extern "C" void kernel_launch(void* const* d_in, const int* in_sizes, int n_in,
                              void* d_out, int out_size)
{
    const int*   src         = (const int*)  d_in[0];
    const int*   dst         = (const int*)  d_in[1];
    const float* t           = (const float*)d_in[2];
    const float* edge_attr   = (const float*)d_in[3];
    const float* memory      = (const float*)d_in[4];
    const float* last_update = (const float*)d_in[5];
    const float* time_w      = (const float*)d_in[6];
    const float* time_b      = (const float*)d_in[7];
    const float* w1          = (const float*)d_in[8];
    const float* b1          = (const float*)d_in[9];
    const float* w2          = (const float*)d_in[10];
    const float* b2          = (const float*)d_in[11];
    float* out = (float*)d_out;

    const int E = in_sizes[0];

    wprep_kernel<<<128, 512>>>(w1);

    cudaFuncSetAttribute(tgn_kernel, cudaFuncAttributeMaxDynamicSharedMemorySize, SMEM_BYTES);
    int grid = (E + TM - 1) / TM;
    tgn_kernel<<<grid, THREADS, SMEM_BYTES>>>(
        src, dst, t, edge_attr, memory, last_update,
        time_w, time_b, b1, w2, b2, out, E);
}

// round 14
// speedup vs baseline: 1.1577x; 1.1577x over previous
#include <cuda_runtime.h>
#include <cuda_fp16.h>
#include <cstdint>

#define TM       64
#define THREADS  256
#define IN_DIM   472
#define HID      128

// ---- smem byte offsets ----
#define A_OFF    0
#define ACS      144                    // A chunk row stride: 64k fp16 = 128B + 16B pad
#define ABUF_STRIDE (64 * ACS)          // 9216 per chunk slot
#define W_OFF    (2 * ABUF_STRIDE)      // 18432
#define WNS      144                    // W n-row stride
#define WBUF_STRIDE (128 * WNS)         // 18432
#define TW_OFF   55296
#define TB_OFF   55696
#define B1_OFF   56096
#define W2_OFF   56608
#define SRC_OFF  57120
#define DST_OFF  57376
#define DT_OFF   57632
#define PART_OFF 57888
#define SMEM_BYTES 58912                // x3 CTA = 176736 <= 228KB

__device__ __align__(16) __half g_w[128 * 512];   // [n][k] fp16

typedef unsigned long long ull;

// ---------------- helpers ----------------
__device__ __forceinline__ uint32_t smem_u32(const void* p) {
    uint32_t a;
    asm("{ .reg .u64 t; cvta.to.shared.u64 t, %1; cvt.u32.u64 %0, t; }" : "=r"(a) : "l"(p));
    return a;
}
__device__ __forceinline__ void ldsm4(uint32_t* r, uint32_t a) {
    asm volatile("ldmatrix.sync.aligned.m8n8.x4.shared.b16 {%0,%1,%2,%3}, [%4];"
        : "=r"(r[0]), "=r"(r[1]), "=r"(r[2]), "=r"(r[3]) : "r"(a));
}
__device__ __forceinline__ void mma16816(float* d, const uint32_t* a, uint32_t b0, uint32_t b1) {
    asm volatile("mma.sync.aligned.m16n8k16.row.col.f32.f16.f16.f32 "
        "{%0,%1,%2,%3}, {%4,%5,%6,%7}, {%8,%9}, {%0,%1,%2,%3};"
        : "+f"(d[0]), "+f"(d[1]), "+f"(d[2]), "+f"(d[3])
        : "r"(a[0]), "r"(a[1]), "r"(a[2]), "r"(a[3]), "r"(b0), "r"(b1));
}
__device__ __forceinline__ void cpasync16(uint32_t s, const void* g) {
    asm volatile("cp.async.cg.shared.global [%0], [%1], 16;" :: "r"(s), "l"(g) : "memory");
}
#define CP_COMMIT() asm volatile("cp.async.commit_group;" ::: "memory")
#define CP_WAIT0()  asm volatile("cp.async.wait_group 0;" ::: "memory")

// ---- packed f32x2 ops ----
__device__ __forceinline__ ull pk2(float x, float y) {
    ull r; asm("mov.b64 %0, {%1, %2};" : "=l"(r) : "f"(x), "f"(y)); return r;
}
__device__ __forceinline__ void upk2(ull v, float& x, float& y) {
    asm("mov.b64 {%0, %1}, %2;" : "=f"(x), "=f"(y) : "l"(v));
}
__device__ __forceinline__ ull fma2(ull a, ull b, ull c) {
    ull d; asm("fma.rn.f32x2 %0, %1, %2, %3;" : "=l"(d) : "l"(a), "l"(b), "l"(c)); return d;
}
__device__ __forceinline__ ull mul2(ull a, ull b) {
    ull d; asm("mul.rn.f32x2 %0, %1, %2;" : "=l"(d) : "l"(a), "l"(b)); return d;
}
__device__ __forceinline__ ull add2(ull a, ull b) {
    ull d; asm("add.rn.f32x2 %0, %1, %2;" : "=l"(d) : "l"(a), "l"(b)); return d;
}
__device__ __forceinline__ ull sub2(ull a, ull b) {
    ull d; asm("sub.rn.f32x2 %0, %1, %2;" : "=l"(d) : "l"(a), "l"(b)); return d;
}

// one packed poly-cos chain: returns cos(x) for packed pair x
__device__ __forceinline__ ull polyChain(ull x) {
    const float inv = 0.15915494309189535f;
    const float mg  = 12582912.0f;
    const ull INV2 = pk2(inv, inv), MAG2 = pk2(mg, mg);
    const ull C1 = pk2(-19.739208802178716f, -19.739208802178716f);
    const ull C2 = pk2( 64.93939402266829f,   64.93939402266829f);
    const ull C3 = pk2(-85.45681720669371f,  -85.45681720669371f);
    const ull C4 = pk2( 60.24464137187666f,   60.24464137187666f);
    const ull C5 = pk2(-26.42625678337438f,  -26.42625678337438f);
    const ull C6 = pk2(  7.903536371318467f,   7.903536371318467f);
    const ull C7 = pk2( -1.714390711088671f,  -1.714390711088671f);
    const ull C0 = pk2(1.0f, 1.0f);
    ull tq = mul2(x, INV2);
    ull kq = add2(tq, MAG2);
    ull nq = sub2(kq, MAG2);
    ull nn = sub2(0ull, nq);
    ull s  = fma2(x, INV2, nn);
    ull u  = mul2(s, s);
    ull P  = fma2(C7, u, C6);
    P = fma2(P, u, C5);
    P = fma2(P, u, C4);
    P = fma2(P, u, C3);
    P = fma2(P, u, C2);
    P = fma2(P, u, C1);
    P = fma2(P, u, C0);
    return P;
}

// ---------------- W prep kernel: fp32 -> fp16, [n][k] ----------------
__global__ void wprep_kernel(const float* __restrict__ w1) {
    int i = blockIdx.x * blockDim.x + threadIdx.x;   // 65536
    int n = i >> 9, k = i & 511;
    float v = (k < IN_DIM) ? w1[(size_t)k * HID + n] : 0.f;
    g_w[(size_t)n * 512 + k] = __float2half(v);
}

// ---------------- main fused kernel ----------------
__global__ void __launch_bounds__(THREADS, 3)
tgn_kernel(const int* __restrict__ src, const int* __restrict__ dst,
           const float* __restrict__ t, const float* __restrict__ edge_attr,
           const float* __restrict__ memory, const float* __restrict__ last_update,
           const float* __restrict__ time_w, const float* __restrict__ time_b,
           const float* __restrict__ b1, const float* __restrict__ w2,
           const float* __restrict__ b2, float* __restrict__ out, int E)
{
    extern __shared__ char sm[];
    const uint32_t smb = smem_u32(sm);
    const int tid  = threadIdx.x;
    const int wid  = tid >> 5;
    const int lane = tid & 31;
    const int eBase = blockIdx.x * TM;

    float* TW   = (float*)(sm + TW_OFF);
    float* TB   = (float*)(sm + TB_OFF);
    float* B1S  = (float*)(sm + B1_OFF);
    float* W2S  = (float*)(sm + W2_OFF);
    int*   SRCI = (int*)(sm + SRC_OFF);
    int*   DSTI = (int*)(sm + DST_OFF);
    float* DTS  = (float*)(sm + DT_OFF);
    float* PART = (float*)(sm + PART_OFF);

    // ---- W chunk copy: 64 k x 128 n fp16 = 16 KB ----
    auto issueW = [&](int g, int b) {
#pragma unroll
        for (int jj = 0; jj < 4; jj++) {
            int idx = tid + THREADS * jj;       // 0..1023
            int n = idx >> 3, k8 = idx & 7;
            const char* gs = (const char*)g_w + ((size_t)n * 512 + g * 64 + k8 * 8) * 2;
            uint32_t sd = smb + W_OFF + b * WBUF_STRIDE + n * WNS + k8 * 16;
            cpasync16(sd, gs);
        }
        CP_COMMIT();
    };
    issueW(0, 0);

    if (tid < 100) { TW[tid] = time_w[tid]; TB[tid] = time_b[tid]; }
    if (tid < HID) { B1S[tid] = b1[tid]; W2S[tid] = w2[tid]; }
    if (tid < TM) {
        int e = eBase + tid;
        int s = 0, d = 0; float dtv = 0.f;
        if (e < E) { s = src[e]; d = dst[e]; dtv = t[e] - last_update[s]; }
        SRCI[tid] = s; DSTI[tid] = d; DTS[tid] = dtv;
    }
    __syncthreads();

    const float2* m2 = reinterpret_cast<const float2*>(memory);     // 50 f2/row
    const float2* e2 = reinterpret_cast<const float2*>(edge_attr);  // 86 f2/row

    // ---- chunk gather: warp = 16 contiguous f2-cols x 2 rows (coalesced) ----
    // thread: cols j = c*32 + g2*16 + (tid&15), g2 = 0,1; rows (tid>>4) + 16m
    auto loadChunk = [&](int c, float2 (*v)[4]) {
        const int r0 = tid >> 4;                // 0..15
#pragma unroll
        for (int g2 = 0; g2 < 2; g2++) {
            const int j = c * 32 + g2 * 16 + (tid & 15);
            float2* vv = v[g2];
            if (j < 50) {
#pragma unroll
                for (int m = 0; m < 4; m++)
                    vv[m] = m2[(size_t)SRCI[r0 + 16 * m] * 50 + j];
            } else if (j < 100) {
                const int cj = j - 50;
#pragma unroll
                for (int m = 0; m < 4; m++)
                    vv[m] = m2[(size_t)DSTI[r0 + 16 * m] * 50 + cj];
            } else if (j < 150) {
                const int tk = (j - 100) * 2;
                if (j < 131) {
                    const float tw0 = TW[tk], tb0 = TB[tk];
                    const float tw1 = TW[tk + 1], tb1 = TB[tk + 1];
#pragma unroll
                    for (int m = 0; m < 4; m++) {
                        float dtv = DTS[r0 + 16 * m];
                        vv[m].x = __cosf(fmaf(dtv, tw0, tb0));
                        vv[m].y = __cosf(fmaf(dtv, tw1, tb1));
                    }
                } else {
                    const ull TWP = pk2(TW[tk], TW[tk + 1]);
                    const ull TBP = pk2(TB[tk], TB[tk + 1]);
#pragma unroll
                    for (int m = 0; m < 4; m++) {
                        float dtv = DTS[r0 + 16 * m];
                        ull P = polyChain(fma2(pk2(dtv, dtv), TWP, TBP));
                        upk2(P, vv[m].x, vv[m].y);
                    }
                }
            } else if (j < 236) {
                const int cj = j - 150;
#pragma unroll
                for (int m = 0; m < 4; m++) {
                    int er = eBase + r0 + 16 * m;
                    er = (er < E) ? er : (E - 1);
                    vv[m] = e2[(size_t)er * 86 + cj];
                }
            } else {
#pragma unroll
                for (int m = 0; m < 4; m++) { vv[m].x = 0.f; vv[m].y = 0.f; }
            }
        }
    };
    auto storeChunk = [&](int c, float2 (*v)[4]) {
        char* base = sm + A_OFF + (c & 1) * ABUF_STRIDE;
        const int r0 = tid >> 4;
#pragma unroll
        for (int g2 = 0; g2 < 2; g2++) {
            const int colB = (g2 * 16 + (tid & 15)) * 4;
#pragma unroll
            for (int m = 0; m < 4; m++)
                *reinterpret_cast<__half2*>(base + (r0 + 16 * m) * ACS + colB) =
                    __floats2half2_rn(v[g2][m].x, v[g2][m].y);
        }
    };

    // ---- warp tile coordinates: 8 warps = 2 row-groups x 4 col-groups ----
    const int rm = (wid & 1) * 32;
    const int cn = (wid >> 1) * 32;
    const uint32_t aLane = (uint32_t)(rm + (lane & 15)) * ACS
                         + (uint32_t)((lane >> 4) << 4);
    const uint32_t bRow  = (uint32_t)(cn + ((lane >> 4) << 3) + (lane & 7)) * WNS
                         + (uint32_t)(((lane >> 3) & 1) << 4);

    float acc[2][4][4];
#pragma unroll
    for (int ma = 0; ma < 2; ma++)
#pragma unroll
        for (int na = 0; na < 4; na++)
#pragma unroll
            for (int q = 0; q < 4; q++) acc[ma][na][q] = 0.f;

    float2 v[2][4];
    loadChunk(0, v);

    // ---- 8 chunks of 64 k; A ring + W double buffer; gathers hidden under mma ----
    for (int g = 0; g < 8; g++) {
        CP_WAIT0();
        __syncthreads();                 // W[g&1] landed; all ldsm of chunk g-2 done
        storeChunk(g, v);
        __syncthreads();                 // A[g&1] visible
        if (g < 7) { issueW(g + 1, (g & 1) ^ 1); loadChunk(g + 1, v); }

        const uint32_t bBase = smb + W_OFF + (uint32_t)(g & 1) * WBUF_STRIDE + bRow;
        const uint32_t aB    = smb + A_OFF + (uint32_t)(g & 1) * ABUF_STRIDE + aLane;
#pragma unroll
        for (int ks = 0; ks < 4; ks++) {
            uint32_t ah[8], bh[8];
            ldsm4(ah,     aB + ks * 32);
            ldsm4(ah + 4, aB + 16 * ACS + ks * 32);
            ldsm4(bh,     bBase + ks * 32);
            ldsm4(bh + 4, bBase + 16 * WNS + ks * 32);
#pragma unroll
            for (int ma = 0; ma < 2; ma++)
#pragma unroll
                for (int na = 0; na < 4; na++)
                    mma16816(acc[ma][na], ah + ma * 4, bh[na * 2], bh[na * 2 + 1]);
        }
    }

    // ---- epilogue: bias + ReLU + w2 dot, reduce over n ----
    float p[2][2] = {{0.f, 0.f}, {0.f, 0.f}};
#pragma unroll
    for (int ma = 0; ma < 2; ma++)
#pragma unroll
        for (int na = 0; na < 4; na++) {
            int n0 = cn + na * 8 + ((lane & 3) << 1);
            float b1a = B1S[n0], b1b = B1S[n0 + 1];
            float w2a = W2S[n0], w2b = W2S[n0 + 1];
            float* d = acc[ma][na];
            p[ma][0] += fmaxf(d[0] + b1a, 0.f) * w2a + fmaxf(d[1] + b1b, 0.f) * w2b;
            p[ma][1] += fmaxf(d[2] + b1a, 0.f) * w2a + fmaxf(d[3] + b1b, 0.f) * w2b;
        }
#pragma unroll
    for (int ma = 0; ma < 2; ma++)
#pragma unroll
        for (int rh = 0; rh < 2; rh++) {
            p[ma][rh] += __shfl_xor_sync(0xffffffffu, p[ma][rh], 1);
            p[ma][rh] += __shfl_xor_sync(0xffffffffu, p[ma][rh], 2);
        }
    if ((lane & 3) == 0) {
        int cw = wid >> 1;
        int r0 = rm + (lane >> 2);
        PART[cw * TM + r0]      = p[0][0];
        PART[cw * TM + r0 + 8]  = p[0][1];
        PART[cw * TM + r0 + 16] = p[1][0];
        PART[cw * TM + r0 + 24] = p[1][1];
    }
    __syncthreads();

    if (tid < TM) {
        int e = eBase + tid;
        if (e < E)
            out[e] = PART[tid] + PART[TM + tid] + PART[2 * TM + tid] + PART[3 * TM + tid] + b2[0];
    }
}

extern "C" void kernel_launch(void* const* d_in, const int* in_sizes, int n_in,
                              void* d_out, int out_size)
{
    const int*   src         = (const int*)  d_in[0];
    const int*   dst         = (const int*)  d_in[1];
    const float* t           = (const float*)d_in[2];
    const float* edge_attr   = (const float*)d_in[3];
    const float* memory      = (const float*)d_in[4];
    const float* last_update = (const float*)d_in[5];
    const float* time_w      = (const float*)d_in[6];
    const float* time_b      = (const float*)d_in[7];
    const float* w1          = (const float*)d_in[8];
    const float* b1          = (const float*)d_in[9];
    const float* w2          = (const float*)d_in[10];
    const float* b2          = (const float*)d_in[11];
    float* out = (float*)d_out;

    const int E = in_sizes[0];

    wprep_kernel<<<128, 512>>>(w1);

    cudaFuncSetAttribute(tgn_kernel, cudaFuncAttributeMaxDynamicSharedMemorySize, SMEM_BYTES);
    int grid = (E + TM - 1) / TM;
    tgn_kernel<<<grid, THREADS, SMEM_BYTES>>>(
        src, dst, t, edge_attr, memory, last_update,
        time_w, time_b, b1, w2, b2, out, E);
}